// round 1
// baseline (speedup 1.0000x reference)
#include <cuda_runtime.h>
#include <cstdint>

#define NSITES 1000000
#define KVOL 27
#define CONV_TPB 256
#define NB_CONV ((NSITES + CONV_TPB - 1) / CONV_TPB)
#define EPSV 1e-5f

// ---------------- scratch (device globals; no allocation allowed) ----------
__device__ float d_h1[(size_t)NSITES * 32];   // 128 MB intermediate
__device__ float d_part[(size_t)NB_CONV * 64]; // per-block [sum(32), sumsq(32)]
__device__ float d_sb1[64];                    // BN1 scale(32), bias(32)
__device__ float d_sb2[64];                    // BN2 scale(32), bias(32)

// ---------------- packed f32x2 helpers -------------------------------------
static __device__ __forceinline__ unsigned long long pack2(float x) {
    unsigned long long r;
    unsigned u = __float_as_uint(x);
    asm("mov.b64 %0, {%1, %1};" : "=l"(r) : "r"(u));
    return r;
}

static __device__ __forceinline__ void fma2(unsigned long long& d,
                                            unsigned long long a,
                                            unsigned long long b) {
    asm("fma.rn.f32x2 %0, %1, %2, %0;" : "+l"(d) : "l"(a), "l"(b));
}

static __device__ __forceinline__ float2 unpack2(unsigned long long v) {
    unsigned lo, hi;
    asm("mov.b64 {%0, %1}, %2;" : "=r"(lo), "=r"(hi) : "l"(v));
    return make_float2(__uint_as_float(lo), __uint_as_float(hi));
}

// ---------------- gather-conv kernel (Cout = 32) ---------------------------
// One thread per output site; 32 fp32 accumulators kept as 16 packed f32x2.
// Weights [27, CIN, 32] cached in dynamic shared memory (broadcast LDS.128).
// Also emits per-block partial sums / sums-of-squares for BatchNorm stats
// (deterministic shuffle-tree + single cross-warp smem reduction).
template <int CIN>
__global__ __launch_bounds__(CONV_TPB) void conv_kernel(
    const float* __restrict__ X, const int* __restrict__ nm,
    const float* __restrict__ W, float* __restrict__ Y) {
    extern __shared__ float smem[];
    const int WN = KVOL * CIN * 32;
    for (int i = threadIdx.x; i < WN; i += CONV_TPB) smem[i] = W[i];
    __syncthreads();

    const int site = blockIdx.x * CONV_TPB + threadIdx.x;

    unsigned long long acc2[16];
#pragma unroll
    for (int c = 0; c < 16; c++) acc2[c] = 0ull;

    if (site < NSITES) {
        const int* nmrow = nm + (long long)site * KVOL;
#pragma unroll 1
        for (int k = 0; k < KVOL; k++) {
            const int idx = nmrow[k];
            float g[CIN];
            if (idx >= 0) {
                const float4* gp =
                    reinterpret_cast<const float4*>(X + (long long)idx * CIN);
#pragma unroll
                for (int j = 0; j < CIN / 4; j++) {
                    float4 t = __ldg(gp + j);
                    g[4 * j + 0] = t.x;
                    g[4 * j + 1] = t.y;
                    g[4 * j + 2] = t.z;
                    g[4 * j + 3] = t.w;
                }
            } else {
#pragma unroll
                for (int j = 0; j < CIN; j++) g[j] = 0.f;
            }
            const float* wk = smem + k * (CIN * 32);
#pragma unroll
            for (int i = 0; i < CIN; i++) {
                const unsigned long long gv = pack2(g[i]);
                const ulonglong2* wp =
                    reinterpret_cast<const ulonglong2*>(wk + i * 32);
#pragma unroll
                for (int c = 0; c < 8; c++) {
                    ulonglong2 w = wp[c];
                    fma2(acc2[2 * c + 0], w.x, gv);
                    fma2(acc2[2 * c + 1], w.y, gv);
                }
            }
        }
    }

    // unpack accumulators (zeros for out-of-range threads)
    float av[32];
#pragma unroll
    for (int c = 0; c < 16; c++) {
        float2 f = unpack2(acc2[c]);
        av[2 * c + 0] = f.x;
        av[2 * c + 1] = f.y;
    }

    if (site < NSITES) {
        float4* yrow = reinterpret_cast<float4*>(Y + (long long)site * 32);
#pragma unroll
        for (int c = 0; c < 8; c++)
            yrow[c] = make_float4(av[4 * c + 0], av[4 * c + 1], av[4 * c + 2],
                                  av[4 * c + 3]);
    }

    // ----- BN partial stats: deterministic tree reduction -----
    __syncthreads();  // weights no longer needed; reuse smem
    const int lane = threadIdx.x & 31;
    const int wrp = threadIdx.x >> 5;
#pragma unroll
    for (int c = 0; c < 32; c++) {
        float s = av[c];
        float q = s * s;
#pragma unroll
        for (int o = 16; o > 0; o >>= 1) {
            s += __shfl_down_sync(0xffffffffu, s, o);
            q += __shfl_down_sync(0xffffffffu, q, o);
        }
        if (lane == 0) {
            smem[wrp * 64 + c] = s;
            smem[wrp * 64 + 32 + c] = q;
        }
    }
    __syncthreads();
    if (threadIdx.x < 64) {
        float s = 0.f;
#pragma unroll
        for (int w = 0; w < 8; w++) s += smem[w * 64 + threadIdx.x];
        d_part[(long long)blockIdx.x * 64 + threadIdx.x] = s;
    }
}

// ---------------- finalize BN stats -> scale/bias --------------------------
__global__ void finalize_kernel(const float* __restrict__ gamma,
                                const float* __restrict__ beta,
                                float* __restrict__ sb) {
    const int c = blockIdx.x;  // 0..31
    float s = 0.f, q = 0.f;
    for (int b = threadIdx.x; b < NB_CONV; b += 256) {
        s += d_part[(long long)b * 64 + c];
        q += d_part[(long long)b * 64 + 32 + c];
    }
    __shared__ float ss[8], qs[8];
    const int lane = threadIdx.x & 31;
    const int wrp = threadIdx.x >> 5;
#pragma unroll
    for (int o = 16; o > 0; o >>= 1) {
        s += __shfl_down_sync(0xffffffffu, s, o);
        q += __shfl_down_sync(0xffffffffu, q, o);
    }
    if (lane == 0) {
        ss[wrp] = s;
        qs[wrp] = q;
    }
    __syncthreads();
    if (threadIdx.x == 0) {
        float S = 0.f, Q = 0.f;
#pragma unroll
        for (int w = 0; w < 8; w++) {
            S += ss[w];
            Q += qs[w];
        }
        const float inv_n = 1.0f / (float)NSITES;
        float mean = S * inv_n;
        float var = Q * inv_n - mean * mean;
        float scale = gamma[c] * rsqrtf(var + EPSV);
        sb[c] = scale;
        sb[32 + c] = beta[c] - mean * scale;
    }
}

// ---------------- in-place BN + ReLU ---------------------------------------
__global__ __launch_bounds__(256) void bnrelu_kernel(float* __restrict__ Y,
                                                     const float* __restrict__ sb) {
    __shared__ float sc[32], bi[32];
    if (threadIdx.x < 32) {
        sc[threadIdx.x] = sb[threadIdx.x];
        bi[threadIdx.x] = sb[32 + threadIdx.x];
    }
    __syncthreads();
    const long long i = (long long)blockIdx.x * 256 + threadIdx.x;  // float4 idx
    float4* p = reinterpret_cast<float4*>(Y);
    float4 v = p[i];
    const int c0 = (int)((i * 4) & 31);
    v.x = fmaxf(0.f, fmaf(v.x, sc[c0 + 0], bi[c0 + 0]));
    v.y = fmaxf(0.f, fmaf(v.y, sc[c0 + 1], bi[c0 + 1]));
    v.z = fmaxf(0.f, fmaf(v.z, sc[c0 + 2], bi[c0 + 2]));
    v.w = fmaxf(0.f, fmaf(v.w, sc[c0 + 3], bi[c0 + 3]));
    p[i] = v;
}

// ---------------- launch ----------------------------------------------------
extern "C" void kernel_launch(void* const* d_in, const int* in_sizes, int n_in,
                              void* d_out, int out_size) {
    const float* feats = (const float*)d_in[0];
    const int* nm = (const int*)d_in[1];
    const float* W1 = (const float*)d_in[2];
    const float* gamma1 = (const float*)d_in[3];
    const float* beta1 = (const float*)d_in[4];
    const float* W2 = (const float*)d_in[5];
    const float* gamma2 = (const float*)d_in[6];
    const float* beta2 = (const float*)d_in[7];
    float* out = (float*)d_out;

    const int smem1 = KVOL * 16 * 32 * (int)sizeof(float);  // 55296 B
    const int smem2 = KVOL * 32 * 32 * (int)sizeof(float);  // 110592 B
    cudaFuncSetAttribute(conv_kernel<16>,
                         cudaFuncAttributeMaxDynamicSharedMemorySize, smem1);
    cudaFuncSetAttribute(conv_kernel<32>,
                         cudaFuncAttributeMaxDynamicSharedMemorySize, smem2);

    void* h1p = nullptr;
    cudaGetSymbolAddress(&h1p, d_h1);
    float* h1 = (float*)h1p;

    void* sb1p = nullptr;
    cudaGetSymbolAddress(&sb1p, d_sb1);
    float* sb1 = (float*)sb1p;
    void* sb2p = nullptr;
    cudaGetSymbolAddress(&sb2p, d_sb2);
    float* sb2 = (float*)sb2p;

    const int ew_blocks = (int)(((long long)NSITES * 32 / 4) / 256);  // 31250

    conv_kernel<16><<<NB_CONV, CONV_TPB, smem1>>>(feats, nm, W1, h1);
    finalize_kernel<<<32, 256>>>(gamma1, beta1, sb1);
    bnrelu_kernel<<<ew_blocks, 256>>>(h1, sb1);
    conv_kernel<32><<<NB_CONV, CONV_TPB, smem2>>>(h1, nm, W2, out);
    finalize_kernel<<<32, 256>>>(gamma2, beta2, sb2);
    bnrelu_kernel<<<ew_blocks, 256>>>(out, sb2);
}

// round 2
// speedup vs baseline: 1.4948x; 1.4948x over previous
#include <cuda_runtime.h>
#include <cstdint>

#define NSITES 1000000
#define KVOL 27
#define CONV_TPB 256
#define T1 4
#define T2 2
#define NB1 ((NSITES + CONV_TPB * T1 - 1) / (CONV_TPB * T1))  // 977
#define NB2 ((NSITES + CONV_TPB * T2 - 1) / (CONV_TPB * T2))  // 1954
#define NB_MAX 1954
#define EPSV 1e-5f

// ---------------- scratch (device globals; no allocation allowed) ----------
__device__ float d_h1[(size_t)NSITES * 32];    // 128 MB intermediate
__device__ float d_part[(size_t)NB_MAX * 64];  // per-block [sum(32), sumsq(32)]
__device__ float d_sb1[64];                    // BN1 scale(32), bias(32)
__device__ float d_sb2[64];                    // BN2 scale(32), bias(32)

// ---------------- packed f32x2 helpers -------------------------------------
static __device__ __forceinline__ unsigned long long pack2(float x) {
    unsigned long long r;
    unsigned u = __float_as_uint(x);
    asm("mov.b64 %0, {%1, %1};" : "=l"(r) : "r"(u));
    return r;
}

static __device__ __forceinline__ void fma2(unsigned long long& d,
                                            unsigned long long a,
                                            unsigned long long b) {
    asm("fma.rn.f32x2 %0, %1, %2, %0;" : "+l"(d) : "l"(a), "l"(b));
}

static __device__ __forceinline__ float2 unpack2(unsigned long long v) {
    unsigned lo, hi;
    asm("mov.b64 {%0, %1}, %2;" : "=r"(lo), "=r"(hi) : "l"(v));
    return make_float2(__uint_as_float(lo), __uint_as_float(hi));
}

// ---------------- gather-conv kernel (Cout = 32, T sites/thread) -----------
// Each thread accumulates T sites x 32 couts; each smem weight load (LDS.128)
// now feeds 2*T FFMA2 instead of 2 -> shifts the kernel from L1-bound to
// FMA-bound. Weights [27, CIN, 32] in dynamic smem. Per-block BN partial
// stats via deterministic shuffle tree.
template <int CIN, int T>
__global__ __launch_bounds__(CONV_TPB) void conv_kernel(
    const float* __restrict__ X, const int* __restrict__ nm,
    const float* __restrict__ W, float* __restrict__ Y) {
    extern __shared__ float smem[];
    const int WN = KVOL * CIN * 32;
    for (int i = threadIdx.x; i < WN; i += CONV_TPB) smem[i] = W[i];
    __syncthreads();

    int site[T];
#pragma unroll
    for (int t = 0; t < T; t++)
        site[t] = blockIdx.x * (CONV_TPB * T) + threadIdx.x + t * CONV_TPB;

    unsigned long long acc2[T][16];
#pragma unroll
    for (int t = 0; t < T; t++)
#pragma unroll
        for (int c = 0; c < 16; c++) acc2[t][c] = 0ull;

#pragma unroll 1
    for (int k = 0; k < KVOL; k++) {
        // gather indices (invalid / tail sites -> -1 -> zero row)
        int idx[T];
#pragma unroll
        for (int t = 0; t < T; t++)
            idx[t] = (site[t] < NSITES)
                         ? __ldg(nm + (long long)site[t] * KVOL + k)
                         : -1;

        // front-batched gathers: T*CIN floats live -> high MLP
        float g[T][CIN];
#pragma unroll
        for (int t = 0; t < T; t++) {
            if (idx[t] >= 0) {
                const float4* gp =
                    reinterpret_cast<const float4*>(X + (long long)idx[t] * CIN);
#pragma unroll
                for (int j = 0; j < CIN / 4; j++) {
                    float4 v = __ldg(gp + j);
                    g[t][4 * j + 0] = v.x;
                    g[t][4 * j + 1] = v.y;
                    g[t][4 * j + 2] = v.z;
                    g[t][4 * j + 3] = v.w;
                }
            } else {
#pragma unroll
                for (int j = 0; j < CIN; j++) g[t][j] = 0.f;
            }
        }

#pragma unroll
        for (int i = 0; i < CIN; i++) {
            unsigned long long gv[T];
#pragma unroll
            for (int t = 0; t < T; t++) gv[t] = pack2(g[t][i]);
            const ulonglong2* wp =
                reinterpret_cast<const ulonglong2*>(smem + (k * CIN + i) * 32);
#pragma unroll
            for (int c = 0; c < 8; c++) {
                ulonglong2 w = wp[c];
#pragma unroll
                for (int t = 0; t < T; t++) {
                    fma2(acc2[t][2 * c + 0], w.x, gv[t]);
                    fma2(acc2[t][2 * c + 1], w.y, gv[t]);
                }
            }
        }
    }

    // unpack, store, and fold T sites into per-thread BN partials
    float sv[32], qv[32];
#pragma unroll
    for (int c = 0; c < 32; c++) {
        sv[c] = 0.f;
        qv[c] = 0.f;
    }
#pragma unroll
    for (int t = 0; t < T; t++) {
        float av[32];
#pragma unroll
        for (int c = 0; c < 16; c++) {
            float2 f = unpack2(acc2[t][c]);
            av[2 * c + 0] = f.x;
            av[2 * c + 1] = f.y;
        }
        if (site[t] < NSITES) {
            float4* yrow =
                reinterpret_cast<float4*>(Y + (long long)site[t] * 32);
#pragma unroll
            for (int c = 0; c < 8; c++)
                yrow[c] = make_float4(av[4 * c + 0], av[4 * c + 1],
                                      av[4 * c + 2], av[4 * c + 3]);
        }
#pragma unroll
        for (int c = 0; c < 32; c++) {
            sv[c] += av[c];
            qv[c] += av[c] * av[c];
        }
    }

    // ----- deterministic block reduction into d_part -----
    __syncthreads();  // weights no longer needed; reuse smem
    const int lane = threadIdx.x & 31;
    const int wrp = threadIdx.x >> 5;
#pragma unroll
    for (int c = 0; c < 32; c++) {
        float s = sv[c];
        float q = qv[c];
#pragma unroll
        for (int o = 16; o > 0; o >>= 1) {
            s += __shfl_down_sync(0xffffffffu, s, o);
            q += __shfl_down_sync(0xffffffffu, q, o);
        }
        if (lane == 0) {
            smem[wrp * 64 + c] = s;
            smem[wrp * 64 + 32 + c] = q;
        }
    }
    __syncthreads();
    if (threadIdx.x < 64) {
        float s = 0.f;
#pragma unroll
        for (int w = 0; w < 8; w++) s += smem[w * 64 + threadIdx.x];
        d_part[(long long)blockIdx.x * 64 + threadIdx.x] = s;
    }
}

// ---------------- finalize BN stats -> scale/bias --------------------------
__global__ void finalize_kernel(const float* __restrict__ gamma,
                                const float* __restrict__ beta,
                                float* __restrict__ sb, int nb) {
    const int c = blockIdx.x;  // 0..31
    float s = 0.f, q = 0.f;
    for (int b = threadIdx.x; b < nb; b += 256) {
        s += d_part[(long long)b * 64 + c];
        q += d_part[(long long)b * 64 + 32 + c];
    }
    __shared__ float ss[8], qs[8];
    const int lane = threadIdx.x & 31;
    const int wrp = threadIdx.x >> 5;
#pragma unroll
    for (int o = 16; o > 0; o >>= 1) {
        s += __shfl_down_sync(0xffffffffu, s, o);
        q += __shfl_down_sync(0xffffffffu, q, o);
    }
    if (lane == 0) {
        ss[wrp] = s;
        qs[wrp] = q;
    }
    __syncthreads();
    if (threadIdx.x == 0) {
        float S = 0.f, Q = 0.f;
#pragma unroll
        for (int w = 0; w < 8; w++) {
            S += ss[w];
            Q += qs[w];
        }
        const float inv_n = 1.0f / (float)NSITES;
        float mean = S * inv_n;
        float var = Q * inv_n - mean * mean;
        float scale = gamma[c] * rsqrtf(var + EPSV);
        sb[c] = scale;
        sb[32 + c] = beta[c] - mean * scale;
    }
}

// ---------------- in-place BN + ReLU ---------------------------------------
__global__ __launch_bounds__(256) void bnrelu_kernel(float* __restrict__ Y,
                                                     const float* __restrict__ sb) {
    __shared__ float sc[32], bi[32];
    if (threadIdx.x < 32) {
        sc[threadIdx.x] = sb[threadIdx.x];
        bi[threadIdx.x] = sb[32 + threadIdx.x];
    }
    __syncthreads();
    const long long i = (long long)blockIdx.x * 256 + threadIdx.x;  // float4 idx
    float4* p = reinterpret_cast<float4*>(Y);
    float4 v = p[i];
    const int c0 = (int)((i * 4) & 31);
    v.x = fmaxf(0.f, fmaf(v.x, sc[c0 + 0], bi[c0 + 0]));
    v.y = fmaxf(0.f, fmaf(v.y, sc[c0 + 1], bi[c0 + 1]));
    v.z = fmaxf(0.f, fmaf(v.z, sc[c0 + 2], bi[c0 + 2]));
    v.w = fmaxf(0.f, fmaf(v.w, sc[c0 + 3], bi[c0 + 3]));
    p[i] = v;
}

// ---------------- launch ----------------------------------------------------
extern "C" void kernel_launch(void* const* d_in, const int* in_sizes, int n_in,
                              void* d_out, int out_size) {
    const float* feats = (const float*)d_in[0];
    const int* nm = (const int*)d_in[1];
    const float* W1 = (const float*)d_in[2];
    const float* gamma1 = (const float*)d_in[3];
    const float* beta1 = (const float*)d_in[4];
    const float* W2 = (const float*)d_in[5];
    const float* gamma2 = (const float*)d_in[6];
    const float* beta2 = (const float*)d_in[7];
    float* out = (float*)d_out;

    const int smem1 = KVOL * 16 * 32 * (int)sizeof(float);  // 55296 B
    const int smem2 = KVOL * 32 * 32 * (int)sizeof(float);  // 110592 B
    cudaFuncSetAttribute(conv_kernel<16, T1>,
                         cudaFuncAttributeMaxDynamicSharedMemorySize, smem1);
    cudaFuncSetAttribute(conv_kernel<32, T2>,
                         cudaFuncAttributeMaxDynamicSharedMemorySize, smem2);

    void* h1p = nullptr;
    cudaGetSymbolAddress(&h1p, d_h1);
    float* h1 = (float*)h1p;
    void* sb1p = nullptr;
    cudaGetSymbolAddress(&sb1p, d_sb1);
    float* sb1 = (float*)sb1p;
    void* sb2p = nullptr;
    cudaGetSymbolAddress(&sb2p, d_sb2);
    float* sb2 = (float*)sb2p;

    const int ew_blocks = (int)(((long long)NSITES * 32 / 4) / 256);  // 31250

    conv_kernel<16, T1><<<NB1, CONV_TPB, smem1>>>(feats, nm, W1, h1);
    finalize_kernel<<<32, 256>>>(gamma1, beta1, sb1, NB1);
    bnrelu_kernel<<<ew_blocks, 256>>>(h1, sb1);
    conv_kernel<32, T2><<<NB2, CONV_TPB, smem2>>>(h1, nm, W2, out);
    finalize_kernel<<<32, 256>>>(gamma2, beta2, sb2, NB2);
    bnrelu_kernel<<<ew_blocks, 256>>>(out, sb2);
}